// round 7
// baseline (speedup 1.0000x reference)
#include <cuda_runtime.h>
#include <math.h>
#include <stdint.h>

#define NT      64             // threads per block, 1 batch element per thread
#define NB      1024           // 65536 / NT
#define TSTEPS  128
#define TT      8              // timesteps per tile
#define NTILES  16             // TSTEPS / TT
#define NSTAGE  3              // cp.async pipeline depth
#define ROW4    7              // float4s per smem row (6 data + 1 pad) -> conflict-free LDS.128
#define TILE4   (NT * ROW4)    // 448 float4 per tile buffer
#define TILEF   (TILE4 * 4)    // 1792 floats per tile buffer

#define L2E 1.4426950408889634f

static __device__ float g_partial[NB];
static __device__ unsigned int g_count = 0;

__device__ __forceinline__ float ex2a(float x) {
    float y; asm("ex2.approx.f32 %0, %1;" : "=f"(y) : "f"(x)); return y;
}
__device__ __forceinline__ float rcpa(float x) {
    float y; asm("rcp.approx.f32 %0, %1;" : "=f"(y) : "f"(x)); return y;
}
__device__ __forceinline__ void cp_async16(uint32_t dst, const float4* src) {
    asm volatile("cp.async.cg.shared.global [%0], [%1], 16;" :: "r"(dst), "l"(src));
}

__global__ __launch_bounds__(NT)
void recdyn_kernel(const float* __restrict__ hist,   // (B,1,T,3)
                   const float* __restrict__ h0,
                   const float* __restrict__ c0,
                   const float* __restrict__ target,
                   const float* __restrict__ Wih,    // (4,3)
                   const float* __restrict__ Whh,    // (4,1)
                   const float* __restrict__ bih,
                   const float* __restrict__ bhh,
                   const float* __restrict__ Wm,     // (3,128)
                   const float* __restrict__ bm,
                   const float* __restrict__ Wv,     // (6,128)
                   const float* __restrict__ bv,
                   float* __restrict__ out)
{
    __shared__ float sw[TSTEPS * 12];        // head weights: row t = [Wm0..2, Wv0..5, pad3]
    __shared__ float sred[NT];
    __shared__ float sbuf[NSTAGE * TILEF];   // 3-stage pipelined x tiles
    __shared__ int slast;

    const int tid = threadIdx.x;
    const int b   = blockIdx.x * NT + tid;

    for (int i = tid; i < TSTEPS * 12; i += NT) {
        int t = i / 12, j = i % 12;
        float v = 0.0f;
        if (j < 3)      v = Wm[j * TSTEPS + t];
        else if (j < 9) v = Wv[(j - 3) * TSTEPS + t];
        sw[i] = v;
    }

    // ---- cp.async staging: 384 f4 slots/tile over 64 threads = 6 each ----
    const int seg0 = tid / 6;
    const int q0   = tid - seg0 * 6;
    const float4* gbase = reinterpret_cast<const float4*>(hist) + (size_t)blockIdx.x * NT * 96;
    const uint32_t sbuf_u32 = (uint32_t)__cvta_generic_to_shared(sbuf);

    // prologue: issue tiles 0 and 1
    #pragma unroll
    for (int pg = 0; pg < 2; ++pg) {
        const float4* src = gbase + pg * 6;
        uint32_t dstb = sbuf_u32 + (uint32_t)(pg * TILEF) * 4u;
        int s = seg0, qq = q0;
        #pragma unroll
        for (int k = 0; k < 6; ++k) {
            cp_async16(dstb + (uint32_t)(s * ROW4 + qq) * 16u,
                       src + (size_t)s * 96 + qq);
            s += 10; qq += 4; if (qq >= 6) { qq -= 6; ++s; }
        }
        asm volatile("cp.async.commit_group;");
    }

    // ---- rotation matrix from last 3 timesteps ----
    const float4* xr = reinterpret_cast<const float4*>(hist + (size_t)b * (TSTEPS * 3));
    float4 r93 = xr[93];
    float4 r94 = xr[94];
    float4 r95 = xr[95];

    float v1x = r95.y, v1y = r95.z, v1z = r95.w;   // t = 127
    float v2x = r94.z, v2y = r94.w, v2z = r95.x;   // t = 126
    float v3x = r93.w, v3y = r94.x, v3z = r94.y;   // t = 125

    float n1 = rsqrtf(v1x*v1x + v1y*v1y + v1z*v1z);
    float b1x = v1x*n1, b1y = v1y*n1, b1z = v1z*n1;

    float p  = v2x*b1x + v2y*b1y + v2z*b1z;
    float a2x = v2x - p*b1x, a2y = v2y - p*b1y, a2z = v2z - p*b1z;
    float n2 = rsqrtf(a2x*a2x + a2y*a2y + a2z*a2z);
    float b2x = a2x*n2, b2y = a2y*n2, b2z = a2z*n2;

    float b3x = b1y*b2z - b1z*b2y;
    float b3y = b1z*b2x - b1x*b2z;
    float b3z = b1x*b2y - b1y*b2x;

    float sgn = (v3x*b3x + v3y*b3y + v3z*b3z) > 0.0f ? 1.0f : -1.0f;
    float c3x = sgn*b3x, c3y = sgn*b3y, c3z = sgn*b3z;

    // ---- fold rotation AND activation scaling into input weights ----
    // gates i,f,o (k=0,1,3): scaled by -log2e  -> sigma = rcp(1 + ex2(gate))
    // gate  g      (k=2)   : scaled by +2log2e -> tanh = fma(-2, rcp(1+ex2(gate)), 1)
    float wihr[12];
    #pragma unroll
    for (int k = 0; k < 12; ++k) wihr[k] = Wih[k];

    float wp[4][3], wh[4], bb[4];
    #pragma unroll
    for (int k = 0; k < 4; ++k) {
        float s = (k == 2) ? (2.0f * L2E) : (-L2E);
        wp[k][0] = s * (wihr[k*3+0]*b1x + wihr[k*3+1]*b2x + wihr[k*3+2]*c3x);
        wp[k][1] = s * (wihr[k*3+0]*b1y + wihr[k*3+1]*b2y + wihr[k*3+2]*c3y);
        wp[k][2] = s * (wihr[k*3+0]*b1z + wihr[k*3+1]*b2z + wihr[k*3+2]*c3z);
        wh[k] = s * Whh[k];
        bb[k] = s * (bih[k] + bhh[k]);
    }

    float h = h0[b], c = c0[b];
    float am0 = 0.f, am1 = 0.f, am2 = 0.f;
    float av0 = 0.f, av1 = 0.f, av2 = 0.f, av3 = 0.f, av4 = 0.f, av5 = 0.f;

    for (int g = 0; g < NTILES; ++g) {
        // issue tile g+2, keep <=2 groups pending so tile g is complete
        if (g + 2 < NTILES) {
            const float4* src = gbase + (g + 2) * 6;
            uint32_t dstb = sbuf_u32 + (uint32_t)(((g + 2) % NSTAGE) * TILEF) * 4u;
            int s = seg0, qq = q0;
            #pragma unroll
            for (int k = 0; k < 6; ++k) {
                cp_async16(dstb + (uint32_t)(s * ROW4 + qq) * 16u,
                           src + (size_t)s * 96 + qq);
                s += 10; qq += 4; if (qq >= 6) { qq -= 6; ++s; }
            }
            asm volatile("cp.async.commit_group;");
            asm volatile("cp.async.wait_group 2;");
        } else if (g + 1 < NTILES) {
            asm volatile("cp.async.wait_group 1;");
        } else {
            asm volatile("cp.async.wait_group 0;");
        }
        __syncthreads();

        const float4* brow = reinterpret_cast<const float4*>(sbuf + (g % NSTAGE) * TILEF) + tid * ROW4;
        const float* swt = sw + g * TT * 12;

        #pragma unroll
        for (int half = 0; half < 2; ++half) {
            float4 p0 = brow[half*3 + 0];
            float4 p1 = brow[half*3 + 1];
            float4 p2 = brow[half*3 + 2];
            float xs[12] = {p0.x,p0.y,p0.z,p0.w, p1.x,p1.y,p1.z,p1.w, p2.x,p2.y,p2.z,p2.w};

            #pragma unroll
            for (int k = 0; k < 4; ++k) {
                const int tl = half * 4 + k;
                float x0 = xs[3*k+0], x1 = xs[3*k+1], x2 = xs[3*k+2];

                float xp0 = fmaf(x0, wp[0][0], fmaf(x1, wp[0][1], fmaf(x2, wp[0][2], bb[0])));
                float xp1 = fmaf(x0, wp[1][0], fmaf(x1, wp[1][1], fmaf(x2, wp[1][2], bb[1])));
                float xp2 = fmaf(x0, wp[2][0], fmaf(x1, wp[2][1], fmaf(x2, wp[2][2], bb[2])));
                float xp3 = fmaf(x0, wp[3][0], fmaf(x1, wp[3][1], fmaf(x2, wp[3][2], bb[3])));

                float gi = fmaf(h, wh[0], xp0);   // = -log2e * raw_i
                float gf = fmaf(h, wh[1], xp1);
                float gg = fmaf(h, wh[2], xp2);   // = +2log2e * raw_g
                float go = fmaf(h, wh[3], xp3);

                float si = rcpa(1.0f + ex2a(gi));             // sigmoid(raw_i)
                float sf = rcpa(1.0f + ex2a(gf));
                float so = rcpa(1.0f + ex2a(go));
                float tg = fmaf(-2.0f, rcpa(1.0f + ex2a(gg)), 1.0f);   // tanh(raw_g)

                c = fmaf(sf, c, si * tg);
                float ec = ex2a(c * (2.0f * L2E));
                float tc = fmaf(-2.0f, rcpa(1.0f + ec), 1.0f);         // tanh(c)
                h = so * tc;

                const float* wr = swt + tl * 12;
                const float4* wv4 = reinterpret_cast<const float4*>(wr);
                float4 w0 = wv4[0];
                float4 w1 = wv4[1];
                float  w8 = wr[8];

                am0 = fmaf(h, w0.x, am0);
                am1 = fmaf(h, w0.y, am1);
                am2 = fmaf(h, w0.z, am2);
                av0 = fmaf(h, w0.w, av0);
                av1 = fmaf(h, w1.x, av1);
                av2 = fmaf(h, w1.y, av2);
                av3 = fmaf(h, w1.z, av3);
                av4 = fmaf(h, w1.w, av4);
                av5 = fmaf(h, w8,   av5);
            }
        }
        __syncthreads();
    }

    // ---- heads + gaussian NLL ----
    float m0 = am0 + bm[0], m1 = am1 + bm[1], m2 = am2 + bm[2];
    float e0 = av0 + bv[0], e1 = av1 + bv[1], e2 = av2 + bv[2];
    float e3 = av3 + bv[3], e4 = av4 + bv[4], e5 = av5 + bv[5];

    float tx = target[b*3+0], ty = target[b*3+1], tz = target[b*3+2];
    float rt0 = tx*b1x + ty*b1y + tz*b1z;
    float rt1 = tx*b2x + ty*b2y + tz*b2z;
    float rt2 = tx*c3x + ty*c3y + tz*c3z;

    float d0 = m0 - rt0, d1 = m1 - rt1, d2 = m2 - rt2;

    float z0 = d0;
    float z1 = d1 - e0 * z0;
    float z2 = d2 - e1 * z0 - e2 * z1;

    float quad = z0*z0*__expf(-e3) + z1*z1*__expf(-e4) + z2*z2*__expf(-e5);
    float val = 0.5f * (__expf(e3) + __expf(e4) + __expf(e5) + quad);

    // ---- block tree reduction (deterministic) ----
    sred[tid] = val;
    __syncthreads();
    #pragma unroll
    for (int off = NT/2; off > 0; off >>= 1) {
        if (tid < off) sred[tid] += sred[tid + off];
        __syncthreads();
    }

    // ---- last-block grid reduction (deterministic fixed order) ----
    if (tid == 0) {
        g_partial[blockIdx.x] = sred[0];
        __threadfence();
        unsigned int n = atomicAdd(&g_count, 1u);
        slast = (n == NB - 1) ? 1 : 0;
    }
    __syncthreads();

    if (slast) {
        float s = 0.0f;
        #pragma unroll
        for (int k = 0; k < NB / NT; ++k)
            s += __ldcg(&g_partial[tid * (NB / NT) + k]);
        sred[tid] = s;
        __syncthreads();
        #pragma unroll
        for (int off = NT/2; off > 0; off >>= 1) {
            if (tid < off) sred[tid] += sred[tid + off];
            __syncthreads();
        }
        if (tid == 0) {
            out[0] = sred[0] * (1.0f / 65536.0f);
            g_count = 0;   // reset for next graph replay
        }
    }
}

extern "C" void kernel_launch(void* const* d_in, const int* in_sizes, int n_in,
                              void* d_out, int out_size)
{
    const float* hist   = (const float*)d_in[0];
    const float* h0     = (const float*)d_in[1];
    const float* c0     = (const float*)d_in[2];
    const float* target = (const float*)d_in[3];
    const float* Wih    = (const float*)d_in[4];
    const float* Whh    = (const float*)d_in[5];
    const float* bih    = (const float*)d_in[6];
    const float* bhh    = (const float*)d_in[7];
    const float* Wm     = (const float*)d_in[8];
    const float* bm     = (const float*)d_in[9];
    const float* Wv     = (const float*)d_in[10];
    const float* bv     = (const float*)d_in[11];

    recdyn_kernel<<<NB, NT>>>(hist, h0, c0, target,
                              Wih, Whh, bih, bhh, Wm, bm, Wv, bv,
                              (float*)d_out);
}

// round 8
// speedup vs baseline: 1.4265x; 1.4265x over previous
#include <cuda_runtime.h>
#include <math.h>
#include <stdint.h>

#define NT      128            // 4 warps/block, 1 batch element per thread
#define NB      512            // 65536 / NT
#define TSTEPS  128
#define TT      8              // timesteps per tile
#define NTILES  16             // TSTEPS / TT
#define NSTAGE  3              // per-warp cp.async ring depth
#define ROW4    7              // float4s per smem row (6 data + 1 pad) -> conflict-free LDS.128
#define WROWS   32             // rows (elements) per warp
#define WTILE4  (WROWS * ROW4) // 224 float4 per warp-stage
#define WBUF4   (NSTAGE * WTILE4)

static __device__ float g_partial[NB];
static __device__ unsigned int g_count = 0;

__device__ __forceinline__ float tanha(float x) {
    float y; asm("tanh.approx.f32 %0, %1;" : "=f"(y) : "f"(x)); return y;
}
__device__ __forceinline__ void cp_async16(uint32_t dst, const float4* src) {
    asm volatile("cp.async.cg.shared.global [%0], [%1], 16;" :: "r"(dst), "l"(src));
}

__global__ __launch_bounds__(NT)
void recdyn_kernel(const float* __restrict__ hist,   // (B,1,T,3)
                   const float* __restrict__ h0,
                   const float* __restrict__ c0,
                   const float* __restrict__ target,
                   const float* __restrict__ Wih,    // (4,3)
                   const float* __restrict__ Whh,    // (4,1)
                   const float* __restrict__ bih,
                   const float* __restrict__ bhh,
                   const float* __restrict__ Wm,     // (3,128)
                   const float* __restrict__ bm,
                   const float* __restrict__ Wv,     // (6,128)
                   const float* __restrict__ bv,
                   float* __restrict__ out)
{
    __shared__ float sw[TSTEPS * 12];           // head weights: row t = [Wm0..2, Wv0..5, pad3]
    __shared__ float sred[NT];
    __shared__ __align__(16) float sbuf[4 * WBUF4 * 4];   // 4 warps x 3-stage rings
    __shared__ int slast;

    const int tid  = threadIdx.x;
    const int lane = tid & 31;
    const int wid  = tid >> 5;
    const int b    = blockIdx.x * NT + tid;

    // ---- stage head weights (transposed), once per block ----
    for (int i = tid; i < TSTEPS * 12; i += NT) {
        int t = i / 12, j = i % 12;
        float v = 0.0f;
        if (j < 3)      v = Wm[j * TSTEPS + t];
        else if (j < 9) v = Wv[(j - 3) * TSTEPS + t];
        sw[i] = v;
    }
    __syncthreads();   // sw ready; no block barriers after this until reduction

    // ---- per-warp staging geometry: 192 f4 slots/tile, 6 per lane ----
    // slot = lane + 32k; seg = slot/6 (row in warp), q = slot%6
    const int seg0 = lane / 6;
    const int q0   = lane - seg0 * 6;
    const float4* gwarp = reinterpret_cast<const float4*>(hist)
                        + ((size_t)blockIdx.x * NT + wid * WROWS) * 96;
    float* wbase = sbuf + (size_t)wid * WBUF4 * 4;
    const uint32_t wbase_u32 = (uint32_t)__cvta_generic_to_shared(wbase);

    // prologue: issue tiles 0 and 1 (warp-private)
    #pragma unroll
    for (int pg = 0; pg < 2; ++pg) {
        const float4* src = gwarp + pg * 6;
        uint32_t dstb = wbase_u32 + (uint32_t)(pg * WTILE4) * 16u;
        int s = seg0, qq = q0;
        #pragma unroll
        for (int k = 0; k < 6; ++k) {
            cp_async16(dstb + (uint32_t)(s * ROW4 + qq) * 16u,
                       src + (size_t)s * 96 + qq);
            // slot += 32: seg += 5, q += 2 (wrap)
            s += 5; qq += 2; if (qq >= 6) { qq -= 6; ++s; }
        }
        asm volatile("cp.async.commit_group;");
    }

    // ---- rotation matrix from last 3 timesteps ----
    const float4* xr = reinterpret_cast<const float4*>(hist + (size_t)b * (TSTEPS * 3));
    float4 r93 = xr[93];
    float4 r94 = xr[94];
    float4 r95 = xr[95];

    float v1x = r95.y, v1y = r95.z, v1z = r95.w;   // t = 127
    float v2x = r94.z, v2y = r94.w, v2z = r95.x;   // t = 126
    float v3x = r93.w, v3y = r94.x, v3z = r94.y;   // t = 125

    float n1 = rsqrtf(v1x*v1x + v1y*v1y + v1z*v1z);
    float b1x = v1x*n1, b1y = v1y*n1, b1z = v1z*n1;

    float p  = v2x*b1x + v2y*b1y + v2z*b1z;
    float a2x = v2x - p*b1x, a2y = v2y - p*b1y, a2z = v2z - p*b1z;
    float n2 = rsqrtf(a2x*a2x + a2y*a2y + a2z*a2z);
    float b2x = a2x*n2, b2y = a2y*n2, b2z = a2z*n2;

    float b3x = b1y*b2z - b1z*b2y;
    float b3y = b1z*b2x - b1x*b2z;
    float b3z = b1x*b2y - b1y*b2x;

    float sgn = (v3x*b3x + v3y*b3y + v3z*b3z) > 0.0f ? 1.0f : -1.0f;
    float c3x = sgn*b3x, c3y = sgn*b3y, c3z = sgn*b3z;

    // ---- fold rotation into input weights; pre-scale i,f,o rows by 0.5 ----
    float wihr[12];
    #pragma unroll
    for (int k = 0; k < 12; ++k) wihr[k] = Wih[k];

    float wp[4][3], wh[4], bb[4];
    #pragma unroll
    for (int k = 0; k < 4; ++k) {
        float s = (k == 2) ? 1.0f : 0.5f;
        wp[k][0] = s * (wihr[k*3+0]*b1x + wihr[k*3+1]*b2x + wihr[k*3+2]*c3x);
        wp[k][1] = s * (wihr[k*3+0]*b1y + wihr[k*3+1]*b2y + wihr[k*3+2]*c3y);
        wp[k][2] = s * (wihr[k*3+0]*b1z + wihr[k*3+1]*b2z + wihr[k*3+2]*c3z);
        wh[k] = s * Whh[k];
        bb[k] = s * (bih[k] + bhh[k]);
    }

    float h = h0[b], c = c0[b];
    float am0 = 0.f, am1 = 0.f, am2 = 0.f;
    float av0 = 0.f, av1 = 0.f, av2 = 0.f, av3 = 0.f, av4 = 0.f, av5 = 0.f;

    for (int g = 0; g < NTILES; ++g) {
        // warp-private: issue tile g+2, wait for tile g
        if (g + 2 < NTILES) {
            const float4* src = gwarp + (g + 2) * 6;
            uint32_t dstb = wbase_u32 + (uint32_t)(((g + 2) % NSTAGE) * WTILE4) * 16u;
            int s = seg0, qq = q0;
            #pragma unroll
            for (int k = 0; k < 6; ++k) {
                cp_async16(dstb + (uint32_t)(s * ROW4 + qq) * 16u,
                           src + (size_t)s * 96 + qq);
                s += 5; qq += 2; if (qq >= 6) { qq -= 6; ++s; }
            }
            asm volatile("cp.async.commit_group;");
            asm volatile("cp.async.wait_group 2;");
        } else if (g + 1 < NTILES) {
            asm volatile("cp.async.wait_group 1;");
        } else {
            asm volatile("cp.async.wait_group 0;");
        }
        __syncwarp();

        const float4* brow = reinterpret_cast<const float4*>(wbase)
                           + (g % NSTAGE) * WTILE4 + lane * ROW4;
        const float* swt = sw + g * TT * 12;

        #pragma unroll
        for (int half = 0; half < 2; ++half) {
            float4 p0 = brow[half*3 + 0];
            float4 p1 = brow[half*3 + 1];
            float4 p2 = brow[half*3 + 2];
            float xs[12] = {p0.x,p0.y,p0.z,p0.w, p1.x,p1.y,p1.z,p1.w, p2.x,p2.y,p2.z,p2.w};

            #pragma unroll
            for (int k = 0; k < 4; ++k) {
                const int tl = half * 4 + k;
                float x0 = xs[3*k+0], x1 = xs[3*k+1], x2 = xs[3*k+2];

                float xp0 = fmaf(x0, wp[0][0], fmaf(x1, wp[0][1], fmaf(x2, wp[0][2], bb[0])));
                float xp1 = fmaf(x0, wp[1][0], fmaf(x1, wp[1][1], fmaf(x2, wp[1][2], bb[1])));
                float xp2 = fmaf(x0, wp[2][0], fmaf(x1, wp[2][1], fmaf(x2, wp[2][2], bb[2])));
                float xp3 = fmaf(x0, wp[3][0], fmaf(x1, wp[3][1], fmaf(x2, wp[3][2], bb[3])));

                float gi = fmaf(h, wh[0], xp0);
                float gf = fmaf(h, wh[1], xp1);
                float gg = fmaf(h, wh[2], xp2);
                float go = fmaf(h, wh[3], xp3);

                float si = fmaf(tanha(gi), 0.5f, 0.5f);
                float sf = fmaf(tanha(gf), 0.5f, 0.5f);
                float so = fmaf(tanha(go), 0.5f, 0.5f);
                float tg = tanha(gg);

                c = fmaf(sf, c, si * tg);
                h = so * tanha(c);

                const float* wr = swt + tl * 12;
                const float4* wv4 = reinterpret_cast<const float4*>(wr);
                float4 w0 = wv4[0];
                float4 w1 = wv4[1];
                float  w8 = wr[8];

                am0 = fmaf(h, w0.x, am0);
                am1 = fmaf(h, w0.y, am1);
                am2 = fmaf(h, w0.z, am2);
                av0 = fmaf(h, w0.w, av0);
                av1 = fmaf(h, w1.x, av1);
                av2 = fmaf(h, w1.y, av2);
                av3 = fmaf(h, w1.z, av3);
                av4 = fmaf(h, w1.w, av4);
                av5 = fmaf(h, w8,   av5);
            }
        }
        __syncwarp();   // all lanes done reading stage (g%NSTAGE) before it is re-written
    }

    // ---- heads + gaussian NLL ----
    float m0 = am0 + bm[0], m1 = am1 + bm[1], m2 = am2 + bm[2];
    float e0 = av0 + bv[0], e1 = av1 + bv[1], e2 = av2 + bv[2];
    float e3 = av3 + bv[3], e4 = av4 + bv[4], e5 = av5 + bv[5];

    float tx = target[b*3+0], ty = target[b*3+1], tz = target[b*3+2];
    float rt0 = tx*b1x + ty*b1y + tz*b1z;
    float rt1 = tx*b2x + ty*b2y + tz*b2z;
    float rt2 = tx*c3x + ty*c3y + tz*c3z;

    float d0 = m0 - rt0, d1 = m1 - rt1, d2 = m2 - rt2;

    float z0 = d0;
    float z1 = d1 - e0 * z0;
    float z2 = d2 - e1 * z0 - e2 * z1;

    float quad = z0*z0*__expf(-e3) + z1*z1*__expf(-e4) + z2*z2*__expf(-e5);
    float val = 0.5f * (__expf(e3) + __expf(e4) + __expf(e5) + quad);

    // ---- block tree reduction (deterministic) ----
    sred[tid] = val;
    __syncthreads();
    #pragma unroll
    for (int off = NT/2; off > 0; off >>= 1) {
        if (tid < off) sred[tid] += sred[tid + off];
        __syncthreads();
    }

    // ---- last-block grid reduction (deterministic fixed order) ----
    if (tid == 0) {
        g_partial[blockIdx.x] = sred[0];
        __threadfence();
        unsigned int n = atomicAdd(&g_count, 1u);
        slast = (n == NB - 1) ? 1 : 0;
    }
    __syncthreads();

    if (slast) {
        float s = 0.0f;
        #pragma unroll
        for (int k = 0; k < NB / NT; ++k)
            s += __ldcg(&g_partial[tid * (NB / NT) + k]);
        sred[tid] = s;
        __syncthreads();
        #pragma unroll
        for (int off = NT/2; off > 0; off >>= 1) {
            if (tid < off) sred[tid] += sred[tid + off];
            __syncthreads();
        }
        if (tid == 0) {
            out[0] = sred[0] * (1.0f / 65536.0f);
            g_count = 0;   // reset for next graph replay
        }
    }
}

extern "C" void kernel_launch(void* const* d_in, const int* in_sizes, int n_in,
                              void* d_out, int out_size)
{
    const float* hist   = (const float*)d_in[0];
    const float* h0     = (const float*)d_in[1];
    const float* c0     = (const float*)d_in[2];
    const float* target = (const float*)d_in[3];
    const float* Wih    = (const float*)d_in[4];
    const float* Whh    = (const float*)d_in[5];
    const float* bih    = (const float*)d_in[6];
    const float* bhh    = (const float*)d_in[7];
    const float* Wm     = (const float*)d_in[8];
    const float* bm     = (const float*)d_in[9];
    const float* Wv     = (const float*)d_in[10];
    const float* bv     = (const float*)d_in[11];

    recdyn_kernel<<<NB, NT>>>(hist, h0, c0, target,
                              Wih, Whh, bih, bhh, Wm, bm, Wv, bv,
                              (float*)d_out);
}

// round 9
// speedup vs baseline: 1.5055x; 1.0554x over previous
#include <cuda_runtime.h>
#include <math.h>
#include <stdint.h>

#define NT      128            // 4 warps/block, 1 batch element per thread
#define NB      512            // 65536 / NT
#define TSTEPS  128
#define TT      8              // timesteps per tile
#define NTILES  16             // TSTEPS / TT
#define NSTAGE  3              // per-warp cp.async ring depth
#define ROW4    7              // float4s per smem row (6 data + 1 pad) -> conflict-free LDS.128
#define WROWS   32             // rows (elements) per warp
#define WTILE4  (WROWS * ROW4) // 224 float4 per warp-stage
#define WBUF4   (NSTAGE * WTILE4)

typedef unsigned long long u64;

static __device__ float g_partial[NB];
static __device__ unsigned int g_count = 0;

__device__ __forceinline__ float tanha(float x) {
    float y; asm("tanh.approx.f32 %0, %1;" : "=f"(y) : "f"(x)); return y;
}
__device__ __forceinline__ u64 pk(float lo, float hi) {
    u64 d; asm("mov.b64 %0, {%1, %2};" : "=l"(d) : "f"(lo), "f"(hi)); return d;
}
__device__ __forceinline__ void upk(float& lo, float& hi, u64 v) {
    asm("mov.b64 {%0, %1}, %2;" : "=f"(lo), "=f"(hi) : "l"(v));
}
__device__ __forceinline__ u64 fma2(u64 a, u64 b, u64 c) {
    u64 d; asm("fma.rn.f32x2 %0, %1, %2, %3;" : "=l"(d) : "l"(a), "l"(b), "l"(c)); return d;
}
__device__ __forceinline__ void cp_async16(uint32_t dst, const float4* src) {
    asm volatile("cp.async.cg.shared.global [%0], [%1], 16;" :: "r"(dst), "l"(src));
}

__global__ __launch_bounds__(NT)
void recdyn_kernel(const float* __restrict__ hist,   // (B,1,T,3)
                   const float* __restrict__ h0,
                   const float* __restrict__ c0,
                   const float* __restrict__ target,
                   const float* __restrict__ Wih,    // (4,3)
                   const float* __restrict__ Whh,    // (4,1)
                   const float* __restrict__ bih,
                   const float* __restrict__ bhh,
                   const float* __restrict__ Wm,     // (3,128)
                   const float* __restrict__ bm,
                   const float* __restrict__ Wv,     // (6,128)
                   const float* __restrict__ bv,
                   float* __restrict__ out)
{
    __shared__ float sw[TSTEPS * 12];           // row t = [Wm0..2, Wv0..5, pad3] (16B aligned rows)
    __shared__ float sred[NT];
    __shared__ __align__(16) float sbuf[4 * WBUF4 * 4];   // 4 warps x 3-stage rings
    __shared__ int slast;

    const int tid  = threadIdx.x;
    const int lane = tid & 31;
    const int wid  = tid >> 5;
    const int b    = blockIdx.x * NT + tid;

    // ---- stage head weights (transposed), once per block ----
    for (int i = tid; i < TSTEPS * 12; i += NT) {
        int t = i / 12, j = i % 12;
        float v = 0.0f;
        if (j < 3)      v = Wm[j * TSTEPS + t];
        else if (j < 9) v = Wv[(j - 3) * TSTEPS + t];
        sw[i] = v;
    }
    __syncthreads();   // sw ready; no block-wide barriers until the reduction

    // ---- per-warp staging: 192 f4 slots/tile, 6 per lane ----
    const int seg0 = lane / 6;
    const int q0   = lane - seg0 * 6;
    const float4* gwarp = reinterpret_cast<const float4*>(hist)
                        + ((size_t)blockIdx.x * NT + wid * WROWS) * 96;
    float* wbase = sbuf + (size_t)wid * WBUF4 * 4;
    const uint32_t wbase_u32 = (uint32_t)__cvta_generic_to_shared(wbase);

    #pragma unroll
    for (int pg = 0; pg < 2; ++pg) {
        const float4* src = gwarp + pg * 6;
        uint32_t dstb = wbase_u32 + (uint32_t)(pg * WTILE4) * 16u;
        int s = seg0, qq = q0;
        #pragma unroll
        for (int k = 0; k < 6; ++k) {
            cp_async16(dstb + (uint32_t)(s * ROW4 + qq) * 16u,
                       src + (size_t)s * 96 + qq);
            s += 5; qq += 2; if (qq >= 6) { qq -= 6; ++s; }
        }
        asm volatile("cp.async.commit_group;");
    }

    // ---- rotation matrix from last 3 timesteps ----
    const float4* xr = reinterpret_cast<const float4*>(hist + (size_t)b * (TSTEPS * 3));
    float4 r93 = xr[93];
    float4 r94 = xr[94];
    float4 r95 = xr[95];

    float v1x = r95.y, v1y = r95.z, v1z = r95.w;   // t = 127
    float v2x = r94.z, v2y = r94.w, v2z = r95.x;   // t = 126
    float v3x = r93.w, v3y = r94.x, v3z = r94.y;   // t = 125

    float n1 = rsqrtf(v1x*v1x + v1y*v1y + v1z*v1z);
    float b1x = v1x*n1, b1y = v1y*n1, b1z = v1z*n1;

    float p  = v2x*b1x + v2y*b1y + v2z*b1z;
    float a2x = v2x - p*b1x, a2y = v2y - p*b1y, a2z = v2z - p*b1z;
    float n2 = rsqrtf(a2x*a2x + a2y*a2y + a2z*a2z);
    float b2x = a2x*n2, b2y = a2y*n2, b2z = a2z*n2;

    float b3x = b1y*b2z - b1z*b2y;
    float b3y = b1z*b2x - b1x*b2z;
    float b3z = b1x*b2y - b1y*b2x;

    float sgn = (v3x*b3x + v3y*b3y + v3z*b3z) > 0.0f ? 1.0f : -1.0f;
    float c3x = sgn*b3x, c3y = sgn*b3y, c3z = sgn*b3z;

    // ---- fold rotation into input weights; pre-scale i,f,o rows by 0.5 ----
    float wihr[12];
    #pragma unroll
    for (int k = 0; k < 12; ++k) wihr[k] = Wih[k];

    float wp[4][3], wh[4], bbs[4];
    #pragma unroll
    for (int k = 0; k < 4; ++k) {
        float s = (k == 2) ? 1.0f : 0.5f;
        wp[k][0] = s * (wihr[k*3+0]*b1x + wihr[k*3+1]*b2x + wihr[k*3+2]*c3x);
        wp[k][1] = s * (wihr[k*3+0]*b1y + wihr[k*3+1]*b2y + wihr[k*3+2]*c3y);
        wp[k][2] = s * (wihr[k*3+0]*b1z + wihr[k*3+1]*b2z + wihr[k*3+2]*c3z);
        wh[k]  = s * Whh[k];
        bbs[k] = s * (bih[k] + bhh[k]);
    }

    // packed gate constants: lanes = (i,f) and (g,o)
    u64 wpIF[3], wpGO[3];
    #pragma unroll
    for (int j = 0; j < 3; ++j) {
        wpIF[j] = pk(wp[0][j], wp[1][j]);
        wpGO[j] = pk(wp[2][j], wp[3][j]);
    }
    const u64 whIF = pk(wh[0], wh[1]),  whGO = pk(wh[2], wh[3]);
    const u64 bbIF = pk(bbs[0], bbs[1]), bbGO = pk(bbs[2], bbs[3]);

    float h = h0[b], c = c0[b];
    // packed head accumulators: (am0,am1) (am2,av0) (av1,av2) (av3,av4) + scalar av5
    u64 acc0 = pk(0.f,0.f), acc1 = pk(0.f,0.f), acc2 = pk(0.f,0.f), acc3 = pk(0.f,0.f);
    float av5 = 0.f;

    for (int g = 0; g < NTILES; ++g) {
        if (g + 2 < NTILES) {
            const float4* src = gwarp + (g + 2) * 6;
            uint32_t dstb = wbase_u32 + (uint32_t)(((g + 2) % NSTAGE) * WTILE4) * 16u;
            int s = seg0, qq = q0;
            #pragma unroll
            for (int k = 0; k < 6; ++k) {
                cp_async16(dstb + (uint32_t)(s * ROW4 + qq) * 16u,
                           src + (size_t)s * 96 + qq);
                s += 5; qq += 2; if (qq >= 6) { qq -= 6; ++s; }
            }
            asm volatile("cp.async.commit_group;");
            asm volatile("cp.async.wait_group 2;");
        } else if (g + 1 < NTILES) {
            asm volatile("cp.async.wait_group 1;");
        } else {
            asm volatile("cp.async.wait_group 0;");
        }
        __syncwarp();

        const float4* brow = reinterpret_cast<const float4*>(wbase)
                           + (g % NSTAGE) * WTILE4 + lane * ROW4;
        const float* swt = sw + g * TT * 12;

        #pragma unroll
        for (int half = 0; half < 2; ++half) {
            float4 p0 = brow[half*3 + 0];
            float4 p1 = brow[half*3 + 1];
            float4 p2 = brow[half*3 + 2];
            float xs[12] = {p0.x,p0.y,p0.z,p0.w, p1.x,p1.y,p1.z,p1.w, p2.x,p2.y,p2.z,p2.w};

            #pragma unroll
            for (int k = 0; k < 4; ++k) {
                const int tl = half * 4 + k;
                float x0 = xs[3*k+0], x1 = xs[3*k+1], x2 = xs[3*k+2];

                u64 X0 = pk(x0, x0);
                u64 X1 = pk(x1, x1);
                u64 X2 = pk(x2, x2);
                u64 H2 = pk(h, h);

                u64 gIF = fma2(H2, whIF, fma2(X0, wpIF[0], fma2(X1, wpIF[1], fma2(X2, wpIF[2], bbIF))));
                u64 gGO = fma2(H2, whGO, fma2(X0, wpGO[0], fma2(X1, wpGO[1], fma2(X2, wpGO[2], bbGO))));

                float gi, gf, gg, go;
                upk(gi, gf, gIF);
                upk(gg, go, gGO);

                float si = fmaf(tanha(gi), 0.5f, 0.5f);
                float sf = fmaf(tanha(gf), 0.5f, 0.5f);
                float so = fmaf(tanha(go), 0.5f, 0.5f);
                float tg = tanha(gg);

                c = fmaf(sf, c, si * tg);
                h = so * tanha(c);

                // head weights: row = 12 floats, pairs (0,1)(2,3)(4,5)(6,7) + w8
                const ulonglong2* wrq = reinterpret_cast<const ulonglong2*>(swt + tl * 12);
                ulonglong2 wq0 = wrq[0];   // (wm0,wm1) (wm2,wv0)
                ulonglong2 wq1 = wrq[1];   // (wv1,wv2) (wv3,wv4)
                float w8 = (swt + tl * 12)[8];

                u64 Hn = pk(h, h);
                acc0 = fma2(Hn, wq0.x, acc0);
                acc1 = fma2(Hn, wq0.y, acc1);
                acc2 = fma2(Hn, wq1.x, acc2);
                acc3 = fma2(Hn, wq1.y, acc3);
                av5  = fmaf(h, w8, av5);
            }
        }
        __syncwarp();
    }

    // ---- unpack heads + gaussian NLL ----
    float am0, am1, am2, av0, av1, av2, av3, av4;
    upk(am0, am1, acc0);
    upk(am2, av0, acc1);
    upk(av1, av2, acc2);
    upk(av3, av4, acc3);

    float m0 = am0 + bm[0], m1 = am1 + bm[1], m2 = am2 + bm[2];
    float e0 = av0 + bv[0], e1 = av1 + bv[1], e2 = av2 + bv[2];
    float e3 = av3 + bv[3], e4 = av4 + bv[4], e5 = av5 + bv[5];

    float tx = target[b*3+0], ty = target[b*3+1], tz = target[b*3+2];
    float rt0 = tx*b1x + ty*b1y + tz*b1z;
    float rt1 = tx*b2x + ty*b2y + tz*b2z;
    float rt2 = tx*c3x + ty*c3y + tz*c3z;

    float d0 = m0 - rt0, d1 = m1 - rt1, d2 = m2 - rt2;

    float z0 = d0;
    float z1 = d1 - e0 * z0;
    float z2 = d2 - e1 * z0 - e2 * z1;

    float quad = z0*z0*__expf(-e3) + z1*z1*__expf(-e4) + z2*z2*__expf(-e5);
    float val = 0.5f * (__expf(e3) + __expf(e4) + __expf(e5) + quad);

    // ---- block tree reduction (deterministic) ----
    sred[tid] = val;
    __syncthreads();
    #pragma unroll
    for (int off = NT/2; off > 0; off >>= 1) {
        if (tid < off) sred[tid] += sred[tid + off];
        __syncthreads();
    }

    // ---- last-block grid reduction (deterministic fixed order) ----
    if (tid == 0) {
        g_partial[blockIdx.x] = sred[0];
        __threadfence();
        unsigned int n = atomicAdd(&g_count, 1u);
        slast = (n == NB - 1) ? 1 : 0;
    }
    __syncthreads();

    if (slast) {
        float s = 0.0f;
        #pragma unroll
        for (int k = 0; k < NB / NT; ++k)
            s += __ldcg(&g_partial[tid * (NB / NT) + k]);
        sred[tid] = s;
        __syncthreads();
        #pragma unroll
        for (int off = NT/2; off > 0; off >>= 1) {
            if (tid < off) sred[tid] += sred[tid + off];
            __syncthreads();
        }
        if (tid == 0) {
            out[0] = sred[0] * (1.0f / 65536.0f);
            g_count = 0;   // reset for next graph replay
        }
    }
}

extern "C" void kernel_launch(void* const* d_in, const int* in_sizes, int n_in,
                              void* d_out, int out_size)
{
    const float* hist   = (const float*)d_in[0];
    const float* h0     = (const float*)d_in[1];
    const float* c0     = (const float*)d_in[2];
    const float* target = (const float*)d_in[3];
    const float* Wih    = (const float*)d_in[4];
    const float* Whh    = (const float*)d_in[5];
    const float* bih    = (const float*)d_in[6];
    const float* bhh    = (const float*)d_in[7];
    const float* Wm     = (const float*)d_in[8];
    const float* bm     = (const float*)d_in[9];
    const float* Wv     = (const float*)d_in[10];
    const float* bv     = (const float*)d_in[11];

    recdyn_kernel<<<NB, NT>>>(hist, h0, c0, target,
                              Wih, Whh, bih, bhh, Wm, bm, Wv, bv,
                              (float*)d_out);
}